// round 7
// baseline (speedup 1.0000x reference)
#include <cuda_runtime.h>
#include <cstdint>

// QuantizationLayer: q = rint(x*8 - 0.5) (round-half-to-even), q in [0,7],
// out bits MSB-first: out[3*i + j] = (q_i >> (2-j)) & 1, as float.
//
// Warp-cooperative tiling (see R4): warp tile = 32 input float4 -> 96 output
// float4; lane-coalesced LDG.128 in, pack 12 bits/lane, one SHFL per output
// vec (4-bit windows never cross a 12-bit pack boundary), lane stores output
// vecs lane/lane+32/lane+64 via coalesced STG.128.
//
// R5/R6 changes:
//  - bit->float without I2F:  bitval = (w & (1<<k)) * (0x3F800000 >> k)
//    (exact: product is bit ? 0x3F800000 : 0 = 1.0f/0.0f). LOP3+IMAD,
//    fixed lat-4 pipes, shortens the SHFL->STG dependency chain ~16cyc
//    and removes 12 cvt-pipe ops per lane-tile.
//  - batch depth 8 (MLP=8 front-batched LDG.128), launch_bounds(256,4)
//    keeps <=64 regs so occupancy stays 32 warps/SM.

static constexpr int TILES_PER_WARP = 8;
static constexpr unsigned FULL = 0xFFFFFFFFu;

__device__ __forceinline__ float4 window_to_float4(unsigned w)
{
    // w: 4-bit window in bits [3:0] (higher bits may be garbage; each
    // component masks exactly one bit). MSB of the window is out .x.
    return make_float4(
        __uint_as_float((w & 8u) * (0x3F800000u >> 3)),
        __uint_as_float((w & 4u) * (0x3F800000u >> 2)),
        __uint_as_float((w & 2u) * (0x3F800000u >> 1)),
        __uint_as_float((w & 1u) *  0x3F800000u));
}

__global__ __launch_bounds__(256, 4) void quant_bits_warp_kernel(
    const float4* __restrict__ in4, float4* __restrict__ out4, unsigned n_tiles)
{
    unsigned warp_g = blockIdx.x * (blockDim.x >> 5) + (threadIdx.x >> 5);
    unsigned lane   = threadIdx.x & 31u;
    unsigned tile0  = warp_g * TILES_PER_WARP;

    // Per-lane shuffle sources / window shifts (same for every tile).
    unsigned p0 = lane / 3u,   s0 = 8u - 4u * (lane - 3u * p0);
    unsigned j1 = lane + 32u;
    unsigned p1 = j1 / 3u,     s1 = 8u - 4u * (j1 - 3u * p1);
    unsigned j2 = lane + 64u;
    unsigned p2 = j2 / 3u,     s2 = 8u - 4u * (j2 - 3u * p2);

    // Front-batched loads (MLP = TILES_PER_WARP)
    float4 v[TILES_PER_WARP];
    #pragma unroll
    for (int i = 0; i < TILES_PER_WARP; i++) {
        unsigned t = tile0 + i;
        if (t < n_tiles) v[i] = __ldcs(&in4[(size_t)t * 32u + lane]);
    }

    #pragma unroll
    for (int i = 0; i < TILES_PER_WARP; i++) {
        unsigned t = tile0 + i;
        if (t >= n_tiles) continue;   // uniform across warp: shuffles converged

        int q0 = __float2int_rn(fmaf(v[i].x, 8.0f, -0.5f));
        int q1 = __float2int_rn(fmaf(v[i].y, 8.0f, -0.5f));
        int q2 = __float2int_rn(fmaf(v[i].z, 8.0f, -0.5f));
        int q3 = __float2int_rn(fmaf(v[i].w, 8.0f, -0.5f));

        // 12-bit pack, stream-MSB-first
        unsigned pack = ((unsigned)q0 << 9) | ((unsigned)q1 << 6)
                      | ((unsigned)q2 << 3) |  (unsigned)q3;

        unsigned w0 = __shfl_sync(FULL, pack, p0) >> s0;
        unsigned w1 = __shfl_sync(FULL, pack, p1) >> s1;
        unsigned w2 = __shfl_sync(FULL, pack, p2) >> s2;

        size_t obase = (size_t)t * 96u;
        __stcs(&out4[obase + lane], window_to_float4(w0));
        __stcs(&out4[obase + j1],   window_to_float4(w1));
        __stcs(&out4[obase + j2],   window_to_float4(w2));
    }
}

// Scalar fallback for elements beyond the last full 128-elem tile
// (never launched for this shape: 33,554,432 = 128 * 262,144).
__global__ void quant_bits_tail_kernel(
    const float* __restrict__ in, float* __restrict__ out,
    unsigned start_elem, unsigned n_elem)
{
    unsigned e = start_elem + blockIdx.x * blockDim.x + threadIdx.x;
    if (e >= n_elem) return;
    int q = __float2int_rn(fmaf(in[e], 8.0f, -0.5f));
    out[3u * e + 0] = (float)((q >> 2) & 1);
    out[3u * e + 1] = (float)((q >> 1) & 1);
    out[3u * e + 2] = (float)( q       & 1);
}

extern "C" void kernel_launch(void* const* d_in, const int* in_sizes, int n_in,
                              void* d_out, int out_size)
{
    const float* x = (const float*)d_in[0];
    float* out = (float*)d_out;
    unsigned n = (unsigned)in_sizes[0];       // 33,554,432
    unsigned n_tiles = n / 128u;              // 262,144 warp tiles

    if (n_tiles > 0) {
        unsigned warps_needed  = (n_tiles + TILES_PER_WARP - 1) / TILES_PER_WARP;
        unsigned warps_per_blk = 8;           // 256 threads
        unsigned blocks = (warps_needed + warps_per_blk - 1) / warps_per_blk;
        quant_bits_warp_kernel<<<blocks, 256>>>(
            (const float4*)x, (float4*)out, n_tiles);
    }
    unsigned done = n_tiles * 128u;
    if (done < n) {
        unsigned tail = n - done;
        quant_bits_tail_kernel<<<(tail + 127) / 128, 128>>>(x, out, done, n);
    }
}

// round 9
// speedup vs baseline: 1.0442x; 1.0442x over previous
#include <cuda_runtime.h>
#include <cstdint>

// QuantizationLayer: q = rint(x*8 - 0.5) (round-half-to-even), q in [0,7],
// out bits MSB-first: out[3*i + j] = (q_i >> (2-j)) & 1, as float.
//
// R8 design (resubmit): TMA bulk-store staging.
//   - block = 256 threads, owns 4096 input elems (16KB) -> 12288 output
//     floats (48KB). Grid = 8192 blocks (exact for this shape).
//   - loads: 4 x LDG.128 per thread, coalesced, streaming.
//   - compute: bit->float without I2F (LOP3+IMAD producing 0x3F800000/0).
//   - each thread writes its own 12 floats to smem (3 x STS.128) -- no
//     shuffles needed, smem absorbs the 48B-stride pattern.
//   - one elected thread emits the whole 48KB tile as a single
//     cp.async.bulk.global.shared::cta (UBLKCP): the write stream leaves
//     via the async proxy in large linear bursts, bypassing L1tex/STG.
//   - 48KB static smem -> 4 blocks/SM: compute of 3 blocks overlaps the
//     bulk-store drain of the 4th.

static constexpr int THREADS          = 256;
static constexpr int VECS_PER_THREAD  = 4;                       // float4 loads
static constexpr int ELEMS_PER_BLOCK  = THREADS * VECS_PER_THREAD * 4;   // 4096
static constexpr int OUT_FLOATS_BLOCK = ELEMS_PER_BLOCK * 3;             // 12288
static constexpr int OUT_BYTES_BLOCK  = OUT_FLOATS_BLOCK * 4;            // 49152

__device__ __forceinline__ uint32_t smem_addr_u32(const void* p)
{
    uint32_t a;
    asm("{ .reg .u64 t; cvta.to.shared.u64 t, %1; cvt.u32.u64 %0, t; }"
        : "=r"(a) : "l"(p));
    return a;
}

__device__ __forceinline__ float bitf(unsigned q, unsigned k)
{
    // (q>>k)&1 as float, no I2F: (q & (1<<k)) * (0x3F800000 >> k)
    return __uint_as_float((q & (1u << k)) * (0x3F800000u >> k));
}

__global__ __launch_bounds__(THREADS) void quant_bits_tma_kernel(
    const float4* __restrict__ in4, float* __restrict__ out)
{
    __shared__ float4 sbuf[OUT_FLOATS_BLOCK / 4];   // 48 KB

    unsigned tid  = threadIdx.x;
    size_t   vbase = (size_t)blockIdx.x * (THREADS * VECS_PER_THREAD);

    // Front-batched coalesced loads (MLP = 4)
    float4 v[VECS_PER_THREAD];
    #pragma unroll
    for (int i = 0; i < VECS_PER_THREAD; i++)
        v[i] = __ldcs(&in4[vbase + (size_t)i * THREADS + tid]);

    #pragma unroll
    for (int i = 0; i < VECS_PER_THREAD; i++) {
        unsigned q0 = (unsigned)__float2int_rn(fmaf(v[i].x, 8.0f, -0.5f));
        unsigned q1 = (unsigned)__float2int_rn(fmaf(v[i].y, 8.0f, -0.5f));
        unsigned q2 = (unsigned)__float2int_rn(fmaf(v[i].z, 8.0f, -0.5f));
        unsigned q3 = (unsigned)__float2int_rn(fmaf(v[i].w, 8.0f, -0.5f));

        // out floats for this float4: 12 consecutive, at vec index g*3
        unsigned g = i * THREADS + tid;
        float4* o = &sbuf[g * 3u];
        o[0] = make_float4(bitf(q0, 2), bitf(q0, 1), bitf(q0, 0), bitf(q1, 2));
        o[1] = make_float4(bitf(q1, 1), bitf(q1, 0), bitf(q2, 2), bitf(q2, 1));
        o[2] = make_float4(bitf(q2, 0), bitf(q3, 2), bitf(q3, 1), bitf(q3, 0));
    }

    __syncthreads();

    if (tid == 0) {
        // Order generic-proxy STS before async-proxy bulk copy
        asm volatile("fence.proxy.async.shared::cta;" ::: "memory");
        float* gdst = out + (size_t)blockIdx.x * OUT_FLOATS_BLOCK;
        uint32_t saddr = smem_addr_u32(sbuf);
        asm volatile(
            "cp.async.bulk.global.shared::cta.bulk_group [%0], [%1], %2;"
            :: "l"(gdst), "r"(saddr), "r"((unsigned)OUT_BYTES_BLOCK)
            : "memory");
        asm volatile("cp.async.bulk.commit_group;" ::: "memory");
        // smem must stay allocated until the bulk copy drains
        asm volatile("cp.async.bulk.wait_group 0;" ::: "memory");
    }
}

// Scalar fallback for elements beyond the last full block chunk
// (never launched for this shape: 33,554,432 = 4096 * 8192).
__global__ void quant_bits_tail_kernel(
    const float* __restrict__ in, float* __restrict__ out,
    unsigned start_elem, unsigned n_elem)
{
    unsigned e = start_elem + blockIdx.x * blockDim.x + threadIdx.x;
    if (e >= n_elem) return;
    int q = __float2int_rn(fmaf(in[e], 8.0f, -0.5f));
    out[3u * e + 0] = (float)((q >> 2) & 1);
    out[3u * e + 1] = (float)((q >> 1) & 1);
    out[3u * e + 2] = (float)( q       & 1);
}

extern "C" void kernel_launch(void* const* d_in, const int* in_sizes, int n_in,
                              void* d_out, int out_size)
{
    const float* x = (const float*)d_in[0];
    float* out = (float*)d_out;
    unsigned n = (unsigned)in_sizes[0];             // 33,554,432
    unsigned n_blocks = n / ELEMS_PER_BLOCK;        // 8192

    if (n_blocks > 0) {
        quant_bits_tma_kernel<<<n_blocks, THREADS>>>((const float4*)x, out);
    }
    unsigned done = n_blocks * ELEMS_PER_BLOCK;
    if (done < n) {
        unsigned tail = n - done;
        quant_bits_tail_kernel<<<(tail + 127) / 128, 128>>>(x, out, done, n);
    }
}